// round 1
// baseline (speedup 1.0000x reference)
#include <cuda_runtime.h>
#include <math.h>

// Problem constants
#define BQ    2
#define LQ    13294            // Lq == S
#define SD    13294
#define MROWS (BQ * LQ)        // 26588
#define DDIM  256
#define NHH   8
#define HDD   32

// Scratch (device globals: allocation-free)
__device__ float g_val[(size_t)MROWS * 256];   // value @ W_val      [B*S, NH*HD]
__device__ float g_off[(size_t)MROWS * 256];   // query @ W_off      [B*Lq, NH*NL*NP*2]
__device__ float g_attn[(size_t)MROWS * 128];  // query @ W_attn     [B*Lq, NH*NL*NP]
__device__ float g_acc[(size_t)MROWS * 256];   // sampled output     [B*Lq, NH*HD]

// ---------------------------------------------------------------------------
// Tiled fp32 GEMM: C[M,N] = A[M,256] @ W[256,N] + bias[N]
// Block tile 128x128, K-tile 8, 256 threads, 8x8 per-thread register tile,
// global->register prefetch to hide load latency behind FFMA.
// Requires N % 128 == 0 (N is 256 or 128 here).
// ---------------------------------------------------------------------------
__global__ __launch_bounds__(256, 2)
void gemm_bias_kernel(const float* __restrict__ A, const float* __restrict__ W,
                      const float* __restrict__ bias, float* __restrict__ C,
                      int M, int N)
{
    __shared__ float As[8][128];   // transposed: As[k][m]
    __shared__ float Bs[8][128];   // Bs[k][n]

    const int tid = threadIdx.x;
    const int bm  = blockIdx.y * 128;
    const int bn  = blockIdx.x * 128;

    // A-tile loader: 256 threads load 256 float4 (128 rows x 8 k)
    const int a_row = tid >> 1;
    const int a_k4  = (tid & 1) * 4;
    // B-tile loader: 8 k-rows x 32 float4-cols
    const int b_row = tid >> 5;
    const int b_col = (tid & 31) * 4;

    const bool a_ok = (bm + a_row) < M;
    const float* Aptr = A + (size_t)(bm + a_row) * 256 + a_k4;
    const float* Wptr = W + (size_t)b_row * N + bn + b_col;

    // compute thread mapping: 8 warps = 4 (M) x 2 (N); warp tile 32x64;
    // lane = 4 (M) x 8 (N); thread tile 8x8
    const int warp = tid >> 5;
    const int lane = tid & 31;
    const int row0 = (warp >> 1) * 32 + (lane >> 3) * 8;
    const int col0 = (warp & 1) * 64 + (lane & 7) * 8;

    float acc[8][8];
#pragma unroll
    for (int i = 0; i < 8; ++i)
#pragma unroll
        for (int j = 0; j < 8; ++j) acc[i][j] = 0.f;

    float4 ra, rb;
    ra = a_ok ? *(const float4*)Aptr : make_float4(0.f, 0.f, 0.f, 0.f);
    rb = *(const float4*)Wptr;

#pragma unroll 1
    for (int kt = 0; kt < 32; ++kt) {
        As[a_k4 + 0][a_row] = ra.x;
        As[a_k4 + 1][a_row] = ra.y;
        As[a_k4 + 2][a_row] = ra.z;
        As[a_k4 + 3][a_row] = ra.w;
        *(float4*)&Bs[b_row][b_col] = rb;
        __syncthreads();

        if (kt < 31) {  // prefetch next tile while computing this one
            const float* Ap = Aptr + (kt + 1) * 8;
            ra = a_ok ? *(const float4*)Ap : make_float4(0.f, 0.f, 0.f, 0.f);
            rb = *(const float4*)(Wptr + (size_t)(kt + 1) * 8 * N);
        }

#pragma unroll
        for (int kk = 0; kk < 8; ++kk) {
            float4 a0 = *(const float4*)&As[kk][row0];
            float4 a1 = *(const float4*)&As[kk][row0 + 4];
            float4 b0 = *(const float4*)&Bs[kk][col0];
            float4 b1 = *(const float4*)&Bs[kk][col0 + 4];
            float av[8] = {a0.x, a0.y, a0.z, a0.w, a1.x, a1.y, a1.z, a1.w};
            float bv[8] = {b0.x, b0.y, b0.z, b0.w, b1.x, b1.y, b1.z, b1.w};
#pragma unroll
            for (int i = 0; i < 8; ++i)
#pragma unroll
                for (int j = 0; j < 8; ++j)
                    acc[i][j] = fmaf(av[i], bv[j], acc[i][j]);
        }
        __syncthreads();
    }

    float bvals[8];
#pragma unroll
    for (int j = 0; j < 8; ++j) bvals[j] = bias[bn + col0 + j];

#pragma unroll
    for (int i = 0; i < 8; ++i) {
        int r = bm + row0 + i;
        if (r < M) {
            float4 v0, v1;
            v0.x = acc[i][0] + bvals[0]; v0.y = acc[i][1] + bvals[1];
            v0.z = acc[i][2] + bvals[2]; v0.w = acc[i][3] + bvals[3];
            v1.x = acc[i][4] + bvals[4]; v1.y = acc[i][5] + bvals[5];
            v1.z = acc[i][6] + bvals[6]; v1.w = acc[i][7] + bvals[7];
            *(float4*)&C[(size_t)r * N + bn + col0]     = v0;
            *(float4*)&C[(size_t)r * N + bn + col0 + 4] = v1;
        }
    }
}

// ---------------------------------------------------------------------------
// Deformable sampling: 1 block per query (8 warps = 8 heads), lane = HD dim.
// Softmax over 16 sample weights per head, bilinear gather from g_val,
// weighted accumulate into g_acc.
// ---------------------------------------------------------------------------
__global__ __launch_bounds__(256)
void deform_sample_kernel(const float* __restrict__ refp)
{
    const int qm   = blockIdx.x;           // 0..MROWS-1
    const int h    = threadIdx.x >> 5;
    const int lane = threadIdx.x & 31;
    const int b    = (qm >= LQ) ? 1 : 0;

    // softmax over the 16 logits of this head (every lane redundantly)
    float logit[16];
    const float* ap = g_attn + (size_t)qm * 128 + h * 16;
    float mx = -1e30f;
#pragma unroll
    for (int j = 0; j < 16; ++j) {
        logit[j] = __ldg(ap + j);
        mx = fmaxf(mx, logit[j]);
    }
    float sum = 0.f;
#pragma unroll
    for (int j = 0; j < 16; ++j) {
        logit[j] = expf(logit[j] - mx);
        sum += logit[j];
    }
    const float inv = 1.f / sum;

    const float* op = g_off + (size_t)qm * 256 + h * 32;  // [NL,NP,2]
    const float* rp = refp + (size_t)qm * 8;              // [NL,2]

    const int   HS[4] = {100, 50, 25, 13};
    const int   ST[4] = {0, 10000, 12500, 13125};

    float acc = 0.f;
#pragma unroll
    for (int l = 0; l < 4; ++l) {
        const float rx = __ldg(rp + l * 2 + 0);
        const float ry = __ldg(rp + l * 2 + 1);
        const int   Wl = HS[l], Hl = HS[l];
        const float Wf = (float)Wl, Hf = (float)Hl;
        const float* vb = g_val + ((size_t)(b * SD + ST[l])) * 256 + h * 32 + lane;
#pragma unroll
        for (int p = 0; p < 4; ++p) {
            const float ox = __ldg(op + (l * 4 + p) * 2 + 0);
            const float oy = __ldg(op + (l * 4 + p) * 2 + 1);
            const float lw = logit[l * 4 + p] * inv;

            // match reference rounding: loc = ref + off/norm ; x = loc*W - 0.5
            const float locx = rx + ox / Wf;
            const float locy = ry + oy / Hf;
            const float x = locx * Wf - 0.5f;
            const float y = locy * Hf - 0.5f;

            const float x0f = floorf(x), y0f = floorf(y);
            const int   x0 = (int)x0f,  y0 = (int)y0f;
            const float wx1 = x - x0f, wx0 = 1.f - wx1;
            const float wy1 = y - y0f, wy0 = 1.f - wy1;

            const bool xin0 = (x0 >= 0) && (x0 < Wl);
            const bool xin1 = (x0 + 1 >= 0) && (x0 + 1 < Wl);
            const bool yin0 = (y0 >= 0) && (y0 < Hl);
            const bool yin1 = (y0 + 1 >= 0) && (y0 + 1 < Hl);

            if (xin0 && yin0) acc = fmaf(lw * wx0 * wy0, __ldg(vb + (size_t)(y0 * Wl + x0) * 256), acc);
            if (xin1 && yin0) acc = fmaf(lw * wx1 * wy0, __ldg(vb + (size_t)(y0 * Wl + x0 + 1) * 256), acc);
            if (xin0 && yin1) acc = fmaf(lw * wx0 * wy1, __ldg(vb + (size_t)((y0 + 1) * Wl + x0) * 256), acc);
            if (xin1 && yin1) acc = fmaf(lw * wx1 * wy1, __ldg(vb + (size_t)((y0 + 1) * Wl + x0 + 1) * 256), acc);
        }
    }
    g_acc[(size_t)qm * 256 + h * 32 + lane] = acc;
}

// ---------------------------------------------------------------------------
extern "C" void kernel_launch(void* const* d_in, const int* in_sizes, int n_in,
                              void* d_out, int out_size)
{
    const float* query  = (const float*)d_in[0];
    const float* refp   = (const float*)d_in[1];
    const float* value  = (const float*)d_in[2];
    const float* W_val  = (const float*)d_in[3];
    const float* b_val  = (const float*)d_in[4];
    const float* W_off  = (const float*)d_in[5];
    const float* b_off  = (const float*)d_in[6];
    const float* W_attn = (const float*)d_in[7];
    const float* b_attn = (const float*)d_in[8];
    const float* W_out  = (const float*)d_in[9];
    const float* b_out  = (const float*)d_in[10];
    float* out = (float*)d_out;

    float *gv, *go, *ga, *gc;
    cudaGetSymbolAddress((void**)&gv, g_val);
    cudaGetSymbolAddress((void**)&go, g_off);
    cudaGetSymbolAddress((void**)&ga, g_attn);
    cudaGetSymbolAddress((void**)&gc, g_acc);

    const int M = MROWS;
    const int mblocks = (M + 127) / 128;   // 208

    dim3 thr(256);
    // 1) val = value @ W_val + b_val
    gemm_bias_kernel<<<dim3(2, mblocks), thr>>>(value, W_val, b_val, gv, M, 256);
    // 2) offsets = query @ W_off + b_off
    gemm_bias_kernel<<<dim3(2, mblocks), thr>>>(query, W_off, b_off, go, M, 256);
    // 3) attn logits = query @ W_attn + b_attn
    gemm_bias_kernel<<<dim3(1, mblocks), thr>>>(query, W_attn, b_attn, ga, M, 128);
    // 4) softmax + bilinear sampling + weighted accumulate
    deform_sample_kernel<<<M, thr>>>(refp);
    // 5) out = acc @ W_out + b_out
    gemm_bias_kernel<<<dim3(2, mblocks), thr>>>(gc, W_out, b_out, out, M, 256);
}

// round 3
// speedup vs baseline: 1.3258x; 1.3258x over previous
#include <cuda_runtime.h>
#include <math.h>

// Problem constants
#define BQ    2
#define LQ    13294            // Lq == S
#define SD    13294
#define MROWS (BQ * LQ)        // 26588
#define DDIM  256
#define NHH   8
#define HDD   32

// Scratch (device globals: allocation-free)
__device__ float g_val[(size_t)MROWS * 256];   // value @ W_val      [B*S, NH*HD]
__device__ float g_off[(size_t)MROWS * 256];   // query @ W_off      [B*Lq, NH*NL*NP*2]
__device__ float g_attn[(size_t)MROWS * 128];  // query @ W_attn     [B*Lq, NH*NL*NP]
__device__ float g_acc[(size_t)MROWS * 256];   // sampled output     [B*Lq, NH*HD]

// ---------------------------------------------------------------------------
// Tiled fp32 GEMM: C[M,N] = A[M,256] @ W[256,N] + bias[N]
// Block tile 128x128, K-tile 8, 256 threads, 8x8 per-thread register tile.
// ---------------------------------------------------------------------------
__global__ __launch_bounds__(256, 2)
void gemm_bias_kernel(const float* __restrict__ A, const float* __restrict__ W,
                      const float* __restrict__ bias, float* __restrict__ C,
                      int M, int N)
{
    __shared__ float As[8][128];   // transposed: As[k][m]
    __shared__ float Bs[8][128];   // Bs[k][n]

    const int tid = threadIdx.x;
    const int bm  = blockIdx.y * 128;
    const int bn  = blockIdx.x * 128;

    const int a_row = tid >> 1;
    const int a_k4  = (tid & 1) * 4;
    const int b_row = tid >> 5;
    const int b_col = (tid & 31) * 4;

    const bool a_ok = (bm + a_row) < M;
    const float* Aptr = A + (size_t)(bm + a_row) * 256 + a_k4;
    const float* Wptr = W + (size_t)b_row * N + bn + b_col;

    const int warp = tid >> 5;
    const int lane = tid & 31;
    const int row0 = (warp >> 1) * 32 + (lane >> 3) * 8;
    const int col0 = (warp & 1) * 64 + (lane & 7) * 8;

    float acc[8][8];
#pragma unroll
    for (int i = 0; i < 8; ++i)
#pragma unroll
        for (int j = 0; j < 8; ++j) acc[i][j] = 0.f;

    float4 ra, rb;
    ra = a_ok ? *(const float4*)Aptr : make_float4(0.f, 0.f, 0.f, 0.f);
    rb = *(const float4*)Wptr;

#pragma unroll 1
    for (int kt = 0; kt < 32; ++kt) {
        As[a_k4 + 0][a_row] = ra.x;
        As[a_k4 + 1][a_row] = ra.y;
        As[a_k4 + 2][a_row] = ra.z;
        As[a_k4 + 3][a_row] = ra.w;
        *(float4*)&Bs[b_row][b_col] = rb;
        __syncthreads();

        if (kt < 31) {
            const float* Ap = Aptr + (kt + 1) * 8;
            ra = a_ok ? *(const float4*)Ap : make_float4(0.f, 0.f, 0.f, 0.f);
            rb = *(const float4*)(Wptr + (size_t)(kt + 1) * 8 * N);
        }

#pragma unroll
        for (int kk = 0; kk < 8; ++kk) {
            float4 a0 = *(const float4*)&As[kk][row0];
            float4 a1 = *(const float4*)&As[kk][row0 + 4];
            float4 b0 = *(const float4*)&Bs[kk][col0];
            float4 b1 = *(const float4*)&Bs[kk][col0 + 4];
            float av[8] = {a0.x, a0.y, a0.z, a0.w, a1.x, a1.y, a1.z, a1.w};
            float bv[8] = {b0.x, b0.y, b0.z, b0.w, b1.x, b1.y, b1.z, b1.w};
#pragma unroll
            for (int i = 0; i < 8; ++i)
#pragma unroll
                for (int j = 0; j < 8; ++j)
                    acc[i][j] = fmaf(av[i], bv[j], acc[i][j]);
        }
        __syncthreads();
    }

    float bvals[8];
#pragma unroll
    for (int j = 0; j < 8; ++j) bvals[j] = bias[bn + col0 + j];

#pragma unroll
    for (int i = 0; i < 8; ++i) {
        int r = bm + row0 + i;
        if (r < M) {
            float4 v0, v1;
            v0.x = acc[i][0] + bvals[0]; v0.y = acc[i][1] + bvals[1];
            v0.z = acc[i][2] + bvals[2]; v0.w = acc[i][3] + bvals[3];
            v1.x = acc[i][4] + bvals[4]; v1.y = acc[i][5] + bvals[5];
            v1.z = acc[i][6] + bvals[6]; v1.w = acc[i][7] + bvals[7];
            *(float4*)&C[(size_t)r * N + bn + col0]     = v0;
            *(float4*)&C[(size_t)r * N + bn + col0 + 4] = v1;
        }
    }
}

// ---------------------------------------------------------------------------
// Deformable sampling v2: warp = (query, head).
// Phase A: one sample per lane (lanes duplicated x2 over 16 samples):
//   softmax via shfl reductions (within each 16-lane half, which holds all 16
//   samples exactly once), bilinear corner weights premultiplied by the
//   softmax weight (OOB -> 0), element offsets; packed float2 {w, off} in smem.
// Phase B: all lanes: 64 x { LDS.64 broadcast, LDG, FFMA } branch-free.
// ---------------------------------------------------------------------------
__constant__ int   c_HS[4] = {100, 50, 25, 13};
__constant__ int   c_ST[4] = {0, 10000, 12500, 13125};
__constant__ float c_HSf[4] = {100.f, 50.f, 25.f, 13.f};

__global__ __launch_bounds__(256)
void deform_sample_kernel(const float* __restrict__ refp)
{
    __shared__ float2 s_wo[8][64];   // [head][sample*4+corner] = {weight, off}

    const int qm   = blockIdx.x;           // 0..MROWS-1
    const int h    = threadIdx.x >> 5;
    const int lane = threadIdx.x & 31;
    const int b    = (qm >= LQ) ? 1 : 0;

    // ---- Phase A: per-sample scalar work, s = lane & 15 (duplicated x2) ----
    {
        const int s = lane & 15;
        const int l = s >> 2;

        float logit = __ldg(g_attn + (size_t)qm * 128 + h * 16 + s);

        // reduction over each 16-lane half: each half holds all 16 samples once
        float mx = logit;
#pragma unroll
        for (int d = 8; d >= 1; d >>= 1)
            mx = fmaxf(mx, __shfl_xor_sync(0xffffffffu, mx, d));
        float e = __expf(logit - mx);
        float sum = e;
#pragma unroll
        for (int d = 8; d >= 1; d >>= 1)
            sum += __shfl_xor_sync(0xffffffffu, sum, d);
        const float lw = e / sum;

        const float2 off2 = *(const float2*)(g_off + (size_t)qm * 256 + h * 32 + s * 2);
        const float2 ref2 = *(const float2*)(refp + (size_t)qm * 8 + l * 2);

        const float Wf = c_HSf[l];
        const int   Wl = c_HS[l];
        const int   rowbase = b * SD + c_ST[l];

        // match reference rounding order: loc = ref + off/norm ; x = loc*W - 0.5
        const float locx = ref2.x + off2.x / Wf;
        const float locy = ref2.y + off2.y / Wf;    // H == W per level
        const float x = locx * Wf - 0.5f;
        const float y = locy * Wf - 0.5f;

        const float x0f = floorf(x), y0f = floorf(y);
        const int   x0 = (int)x0f,  y0 = (int)y0f;
        const float wx1 = x - x0f, wx0 = 1.f - wx1;
        const float wy1 = y - y0f, wy0 = 1.f - wy1;

        const int x1 = x0 + 1, y1 = y0 + 1;
        const float mx0 = (x0 >= 0 && x0 < Wl) ? 1.f : 0.f;
        const float mx1 = (x1 >= 0 && x1 < Wl) ? 1.f : 0.f;
        const float my0 = (y0 >= 0 && y0 < Wl) ? 1.f : 0.f;
        const float my1 = (y1 >= 0 && y1 < Wl) ? 1.f : 0.f;

        const int xc0 = min(max(x0, 0), Wl - 1);
        const int xc1 = min(max(x1, 0), Wl - 1);
        const int yc0 = min(max(y0, 0), Wl - 1);
        const int yc1 = min(max(y1, 0), Wl - 1);

        const int base = rowbase * 256 + h * 32;
        if (lane < 16) {
            float2 v;
            v.x = lw * wx0 * wy0 * mx0 * my0;
            v.y = __int_as_float(base + (yc0 * Wl + xc0) * 256);
            s_wo[h][s * 4 + 0] = v;
            v.x = lw * wx1 * wy0 * mx1 * my0;
            v.y = __int_as_float(base + (yc0 * Wl + xc1) * 256);
            s_wo[h][s * 4 + 1] = v;
            v.x = lw * wx0 * wy1 * mx0 * my1;
            v.y = __int_as_float(base + (yc1 * Wl + xc0) * 256);
            s_wo[h][s * 4 + 2] = v;
            v.x = lw * wx1 * wy1 * mx1 * my1;
            v.y = __int_as_float(base + (yc1 * Wl + xc1) * 256);
            s_wo[h][s * 4 + 3] = v;
        }
    }
    __syncwarp();

    // ---- Phase B: branch-free gather + weighted accumulate (4 partials) ----
    const float* vl = g_val + lane;
    float a0 = 0.f, a1 = 0.f, a2 = 0.f, a3 = 0.f;
#pragma unroll
    for (int i = 0; i < 64; i += 4) {
        const float2 w0 = s_wo[h][i + 0];
        const float2 w1 = s_wo[h][i + 1];
        const float2 w2 = s_wo[h][i + 2];
        const float2 w3 = s_wo[h][i + 3];
        a0 = fmaf(w0.x, __ldg(vl + __float_as_int(w0.y)), a0);
        a1 = fmaf(w1.x, __ldg(vl + __float_as_int(w1.y)), a1);
        a2 = fmaf(w2.x, __ldg(vl + __float_as_int(w2.y)), a2);
        a3 = fmaf(w3.x, __ldg(vl + __float_as_int(w3.y)), a3);
    }
    g_acc[(size_t)qm * 256 + h * 32 + lane] = (a0 + a1) + (a2 + a3);
}

// ---------------------------------------------------------------------------
extern "C" void kernel_launch(void* const* d_in, const int* in_sizes, int n_in,
                              void* d_out, int out_size)
{
    const float* query  = (const float*)d_in[0];
    const float* refp   = (const float*)d_in[1];
    const float* value  = (const float*)d_in[2];
    const float* W_val  = (const float*)d_in[3];
    const float* b_val  = (const float*)d_in[4];
    const float* W_off  = (const float*)d_in[5];
    const float* b_off  = (const float*)d_in[6];
    const float* W_attn = (const float*)d_in[7];
    const float* b_attn = (const float*)d_in[8];
    const float* W_out  = (const float*)d_in[9];
    const float* b_out  = (const float*)d_in[10];
    float* out = (float*)d_out;

    float *gv, *go, *ga, *gc;
    cudaGetSymbolAddress((void**)&gv, g_val);
    cudaGetSymbolAddress((void**)&go, g_off);
    cudaGetSymbolAddress((void**)&ga, g_attn);
    cudaGetSymbolAddress((void**)&gc, g_acc);

    const int M = MROWS;
    const int mblocks = (M + 127) / 128;   // 208

    dim3 thr(256);
    gemm_bias_kernel<<<dim3(2, mblocks), thr>>>(value, W_val, b_val, gv, M, 256);
    gemm_bias_kernel<<<dim3(2, mblocks), thr>>>(query, W_off, b_off, go, M, 256);
    gemm_bias_kernel<<<dim3(1, mblocks), thr>>>(query, W_attn, b_attn, ga, M, 128);
    deform_sample_kernel<<<M, thr>>>(refp);
    gemm_bias_kernel<<<dim3(2, mblocks), thr>>>(gc, W_out, b_out, out, M, 256);
}

// round 8
// speedup vs baseline: 2.5222x; 1.9023x over previous
#include <cuda_runtime.h>
#include <cuda_bf16.h>
#include <stdint.h>
#include <math.h>

// Problem constants
#define BQ    2
#define LQ    13294
#define SD    13294
#define MROWS (BQ * LQ)        // 26588

// Scratch (device globals: allocation-free)
__device__ float g_val[(size_t)MROWS * 256];
__device__ float g_off[(size_t)MROWS * 256];
__device__ float g_attn[(size_t)MROWS * 128];
__device__ float g_acc[(size_t)MROWS * 256];

// ===========================================================================
// Helpers
// ===========================================================================
__device__ __forceinline__ uint32_t smem_u32(const void* p) {
    uint32_t a;
    asm("{ .reg .u64 t; cvta.to.shared.u64 t, %1; cvt.u32.u64 %0, t; }"
        : "=r"(a) : "l"(p));
    return a;
}

#define SW128(x) ((uint32_t)(x) ^ ((((uint32_t)(x)) >> 3) & 0x70u))

__device__ __forceinline__ uint32_t pack_bf2(__nv_bfloat16 a, __nv_bfloat16 b) {
    __nv_bfloat162 t = __halves2bfloat162(a, b);
    return *reinterpret_cast<uint32_t*>(&t);
}

__device__ __forceinline__ void ldsm_x4(uint32_t* r, uint32_t addr) {
    asm volatile("ldmatrix.sync.aligned.m8n8.x4.shared.b16 {%0,%1,%2,%3}, [%4];"
        : "=r"(r[0]), "=r"(r[1]), "=r"(r[2]), "=r"(r[3]) : "r"(addr));
}

__device__ __forceinline__ void mma16816(float* d, const uint32_t* a, const uint32_t* b) {
    asm volatile(
        "mma.sync.aligned.m16n8k16.row.col.f32.bf16.bf16.f32 "
        "{%0,%1,%2,%3}, {%4,%5,%6,%7}, {%8,%9}, {%0,%1,%2,%3};"
        : "+f"(d[0]), "+f"(d[1]), "+f"(d[2]), "+f"(d[3])
        : "r"(a[0]), "r"(a[1]), "r"(a[2]), "r"(a[3]), "r"(b[0]), "r"(b[1]));
}

// ===========================================================================
// Tensor-core GEMM via mma.sync: C[M,N] = A[M,256] @ W[256,N] + bias.
// fp32 accuracy via bf16 3-split (AhiBhi + AloBhi + AhiBlo).
// Block tile 128x128, K chunked by 64 (4 chunks), 256 threads (8 warps =
// 2M x 4N, warp tile 64x32 = 4x4 m16n8k16 frags). SW128-swizzled smem.
// ===========================================================================
#define SM_A_HI 0
#define SM_A_LO 16384
#define SM_B_HI 32768
#define SM_B_LO 49152
#define SM_TOTAL 65536

__global__ __launch_bounds__(256, 2)
void gemm_tc_kernel(const float* __restrict__ A, const float* __restrict__ W,
                    const float* __restrict__ bias, float* __restrict__ C,
                    int M, int N)
{
    extern __shared__ char smem[];
    const uint32_t sb  = smem_u32(smem);
    const int tid  = threadIdx.x;
    const int wid  = tid >> 5;
    const int lane = tid & 31;
    const int bm   = blockIdx.y * 128;
    const int bn   = blockIdx.x * 128;

    const int wm = wid >> 2;      // 0..1  (64-row slab)
    const int wn = wid & 3;       // 0..3  (32-col slab)

    float acc[4][4][4];
#pragma unroll
    for (int i = 0; i < 4; ++i)
#pragma unroll
        for (int j = 0; j < 4; ++j)
#pragma unroll
            for (int r = 0; r < 4; ++r) acc[i][j][r] = 0.f;

    // precomputed ldmatrix smem offsets (k-step part added in loop)
    // A: row = m0 + (lane&15), colbyte = kk*32 + ((lane>>4)&1)*16
    // B: row = nbase + ((lane>>4)&1)*8 + (lane&7), colbyte = kk*32 + ((lane>>3)&1)*16
    const int a_row_l = lane & 15;
    const int a_cb_l  = ((lane >> 4) & 1) * 16;
    const int b_row_l = ((lane >> 4) & 1) * 8 + (lane & 7);
    const int b_cb_l  = ((lane >> 3) & 1) * 16;

#pragma unroll 1
    for (int c = 0; c < 4; ++c) {
        __syncthreads();   // previous iter's ldmatrix readers done

        // ---- load + split A chunk: rows 0..127, k c*64..c*64+63 ----
#pragma unroll
        for (int i = 0; i < 8; ++i) {
            int idx = i * 256 + tid;           // 0..2047 float4 tasks
            int row = idx >> 4;                // 0..127
            int k4  = (idx & 15) << 2;         // 0..60
            int gr  = bm + row;
            float4 v = make_float4(0.f, 0.f, 0.f, 0.f);
            if (gr < M) v = *(const float4*)(A + (size_t)gr * 256 + c * 64 + k4);
            __nv_bfloat16 h0 = __float2bfloat16_rn(v.x);
            __nv_bfloat16 h1 = __float2bfloat16_rn(v.y);
            __nv_bfloat16 h2 = __float2bfloat16_rn(v.z);
            __nv_bfloat16 h3 = __float2bfloat16_rn(v.w);
            __nv_bfloat16 l0 = __float2bfloat16_rn(v.x - __bfloat162float(h0));
            __nv_bfloat16 l1 = __float2bfloat16_rn(v.y - __bfloat162float(h1));
            __nv_bfloat16 l2 = __float2bfloat16_rn(v.z - __bfloat162float(h2));
            __nv_bfloat16 l3 = __float2bfloat16_rn(v.w - __bfloat162float(h3));
            uint32_t off = SW128(row * 128 + k4 * 2);
            *(uint32_t*)(smem + SM_A_HI + off)     = pack_bf2(h0, h1);
            *(uint32_t*)(smem + SM_A_HI + off + 4) = pack_bf2(h2, h3);
            *(uint32_t*)(smem + SM_A_LO + off)     = pack_bf2(l0, l1);
            *(uint32_t*)(smem + SM_A_LO + off + 4) = pack_bf2(l2, l3);
        }

        // ---- load + split + transpose B chunk: B_smem[n][k] = W[k][bn+n] ----
#pragma unroll
        for (int i = 0; i < 4; ++i) {
            int idx = i * 256 + tid;           // 0..1023 tasks
            int kg  = idx >> 7;                // 0..7 (k-group of 8)
            int n   = idx & 127;
            const float* wp = W + (size_t)(c * 64 + kg * 8) * N + bn + n;
            uint32_t hi[4], lo[4];
#pragma unroll
            for (int j = 0; j < 4; ++j) {
                float va = wp[(size_t)(2 * j) * N];
                float vb = wp[(size_t)(2 * j + 1) * N];
                __nv_bfloat16 ha = __float2bfloat16_rn(va);
                __nv_bfloat16 hb = __float2bfloat16_rn(vb);
                hi[j] = pack_bf2(ha, hb);
                lo[j] = pack_bf2(__float2bfloat16_rn(va - __bfloat162float(ha)),
                                 __float2bfloat16_rn(vb - __bfloat162float(hb)));
            }
            uint32_t off = SW128(n * 128 + kg * 16);
            *(uint4*)(smem + SM_B_HI + off) = make_uint4(hi[0], hi[1], hi[2], hi[3]);
            *(uint4*)(smem + SM_B_LO + off) = make_uint4(lo[0], lo[1], lo[2], lo[3]);
        }

        __syncthreads();

        // ---- tensor-core compute on this chunk: 4 k-steps of 16 ----
#pragma unroll
        for (int kk = 0; kk < 4; ++kk) {
            uint32_t ah[4][4], al[4][4];
#pragma unroll
            for (int i = 0; i < 4; ++i) {
                uint32_t off = SW128((wm * 64 + i * 16 + a_row_l) * 128 +
                                     kk * 32 + a_cb_l);
                ldsm_x4(ah[i], sb + SM_A_HI + off);
                ldsm_x4(al[i], sb + SM_A_LO + off);
            }
#pragma unroll
            for (int j2 = 0; j2 < 2; ++j2) {
                uint32_t bh[4], bl[4];
                uint32_t off = SW128((wn * 32 + j2 * 16 + b_row_l) * 128 +
                                     kk * 32 + b_cb_l);
                ldsm_x4(bh, sb + SM_B_HI + off);
                ldsm_x4(bl, sb + SM_B_LO + off);
#pragma unroll
                for (int jj = 0; jj < 2; ++jj) {
                    int j = j2 * 2 + jj;
#pragma unroll
                    for (int i = 0; i < 4; ++i) {
                        mma16816(acc[i][j], ah[i], bh + jj * 2);
                        mma16816(acc[i][j], al[i], bh + jj * 2);
                        mma16816(acc[i][j], ah[i], bl + jj * 2);
                    }
                }
            }
        }
    }

    // ---- epilogue: direct global stores + bias ----
    const int tr = lane >> 2;          // 0..7
    const int tc = (lane & 3) * 2;     // 0,2,4,6
#pragma unroll
    for (int i = 0; i < 4; ++i) {
        const int row0 = bm + wm * 64 + i * 16 + tr;
        const int row1 = row0 + 8;
#pragma unroll
        for (int j = 0; j < 4; ++j) {
            const int col = bn + wn * 32 + j * 8 + tc;
            const float2 bv = *(const float2*)(bias + col);
            if (row0 < M) {
                float2 o;
                o.x = acc[i][j][0] + bv.x;
                o.y = acc[i][j][1] + bv.y;
                *(float2*)(C + (size_t)row0 * N + col) = o;
            }
            if (row1 < M) {
                float2 o;
                o.x = acc[i][j][2] + bv.x;
                o.y = acc[i][j][3] + bv.y;
                *(float2*)(C + (size_t)row1 * N + col) = o;
            }
        }
    }
}

// ===========================================================================
// Deformable sampling (unchanged from R3 pass)
// ===========================================================================
__constant__ int   c_HS[4] = {100, 50, 25, 13};
__constant__ int   c_ST[4] = {0, 10000, 12500, 13125};
__constant__ float c_HSf[4] = {100.f, 50.f, 25.f, 13.f};

__global__ __launch_bounds__(256)
void deform_sample_kernel(const float* __restrict__ refp)
{
    __shared__ float2 s_wo[8][64];

    const int qm   = blockIdx.x;
    const int h    = threadIdx.x >> 5;
    const int lane = threadIdx.x & 31;
    const int b    = (qm >= LQ) ? 1 : 0;

    {
        const int s = lane & 15;
        const int l = s >> 2;

        float logit = __ldg(g_attn + (size_t)qm * 128 + h * 16 + s);
        float mx = logit;
#pragma unroll
        for (int d = 8; d >= 1; d >>= 1)
            mx = fmaxf(mx, __shfl_xor_sync(0xffffffffu, mx, d));
        float e = __expf(logit - mx);
        float sum = e;
#pragma unroll
        for (int d = 8; d >= 1; d >>= 1)
            sum += __shfl_xor_sync(0xffffffffu, sum, d);
        const float lw = e / sum;

        const float2 off2 = *(const float2*)(g_off + (size_t)qm * 256 + h * 32 + s * 2);
        const float2 ref2 = *(const float2*)(refp + (size_t)qm * 8 + l * 2);

        const float Wf = c_HSf[l];
        const int   Wl = c_HS[l];
        const int   rowbase = b * SD + c_ST[l];

        const float locx = ref2.x + off2.x / Wf;
        const float locy = ref2.y + off2.y / Wf;
        const float x = locx * Wf - 0.5f;
        const float y = locy * Wf - 0.5f;

        const float x0f = floorf(x), y0f = floorf(y);
        const int   x0 = (int)x0f,  y0 = (int)y0f;
        const float wx1 = x - x0f, wx0 = 1.f - wx1;
        const float wy1 = y - y0f, wy0 = 1.f - wy1;

        const int x1 = x0 + 1, y1 = y0 + 1;
        const float mx0 = (x0 >= 0 && x0 < Wl) ? 1.f : 0.f;
        const float mx1 = (x1 >= 0 && x1 < Wl) ? 1.f : 0.f;
        const float my0 = (y0 >= 0 && y0 < Wl) ? 1.f : 0.f;
        const float my1 = (y1 >= 0 && y1 < Wl) ? 1.f : 0.f;

        const int xc0 = min(max(x0, 0), Wl - 1);
        const int xc1 = min(max(x1, 0), Wl - 1);
        const int yc0 = min(max(y0, 0), Wl - 1);
        const int yc1 = min(max(y1, 0), Wl - 1);

        const int base = rowbase * 256 + h * 32;
        if (lane < 16) {
            float2 v;
            v.x = lw * wx0 * wy0 * mx0 * my0;
            v.y = __int_as_float(base + (yc0 * Wl + xc0) * 256);
            s_wo[h][s * 4 + 0] = v;
            v.x = lw * wx1 * wy0 * mx1 * my0;
            v.y = __int_as_float(base + (yc0 * Wl + xc1) * 256);
            s_wo[h][s * 4 + 1] = v;
            v.x = lw * wx0 * wy1 * mx0 * my1;
            v.y = __int_as_float(base + (yc1 * Wl + xc0) * 256);
            s_wo[h][s * 4 + 2] = v;
            v.x = lw * wx1 * wy1 * mx1 * my1;
            v.y = __int_as_float(base + (yc1 * Wl + xc1) * 256);
            s_wo[h][s * 4 + 3] = v;
        }
    }
    __syncwarp();

    const float* vl = g_val + lane;
    float a0 = 0.f, a1 = 0.f, a2 = 0.f, a3 = 0.f;
#pragma unroll
    for (int i = 0; i < 64; i += 4) {
        const float2 w0 = s_wo[h][i + 0];
        const float2 w1 = s_wo[h][i + 1];
        const float2 w2 = s_wo[h][i + 2];
        const float2 w3 = s_wo[h][i + 3];
        a0 = fmaf(w0.x, __ldg(vl + __float_as_int(w0.y)), a0);
        a1 = fmaf(w1.x, __ldg(vl + __float_as_int(w1.y)), a1);
        a2 = fmaf(w2.x, __ldg(vl + __float_as_int(w2.y)), a2);
        a3 = fmaf(w3.x, __ldg(vl + __float_as_int(w3.y)), a3);
    }
    g_acc[(size_t)qm * 256 + h * 32 + lane] = (a0 + a1) + (a2 + a3);
}

// ===========================================================================
extern "C" void kernel_launch(void* const* d_in, const int* in_sizes, int n_in,
                              void* d_out, int out_size)
{
    const float* query  = (const float*)d_in[0];
    const float* refp   = (const float*)d_in[1];
    const float* value  = (const float*)d_in[2];
    const float* W_val  = (const float*)d_in[3];
    const float* b_val  = (const float*)d_in[4];
    const float* W_off  = (const float*)d_in[5];
    const float* b_off  = (const float*)d_in[6];
    const float* W_attn = (const float*)d_in[7];
    const float* b_attn = (const float*)d_in[8];
    const float* W_out  = (const float*)d_in[9];
    const float* b_out  = (const float*)d_in[10];
    float* out = (float*)d_out;

    float *gv, *go, *ga, *gc;
    cudaGetSymbolAddress((void**)&gv, g_val);
    cudaGetSymbolAddress((void**)&go, g_off);
    cudaGetSymbolAddress((void**)&ga, g_attn);
    cudaGetSymbolAddress((void**)&gc, g_acc);

    cudaFuncSetAttribute(gemm_tc_kernel,
                         cudaFuncAttributeMaxDynamicSharedMemorySize, SM_TOTAL);

    const int M = MROWS;
    const int mblocks = (M + 127) / 128;   // 208
    dim3 thr(256);

    gemm_tc_kernel<<<dim3(2, mblocks), thr, SM_TOTAL>>>(value, W_val, b_val, gv, M, 256);
    gemm_tc_kernel<<<dim3(2, mblocks), thr, SM_TOTAL>>>(query, W_off, b_off, go, M, 256);
    gemm_tc_kernel<<<dim3(1, mblocks), thr, SM_TOTAL>>>(query, W_attn, b_attn, ga, M, 128);
    deform_sample_kernel<<<M, thr>>>(refp);
    gemm_tc_kernel<<<dim3(2, mblocks), thr, SM_TOTAL>>>(gc, W_out, b_out, out, M, 256);
}